// round 1
// baseline (speedup 1.0000x reference)
#include <cuda_runtime.h>
#include <cuda_bf16.h>
#include <cstdint>

// Problem constants
#define BB 32
#define NN 64
#define FF 1280
#define HH 512
#define EE 512
#define VV 10000
#define TT 80
#define G4 2048          // 4*H

// Output layout (pytree flatten order: decoder_outputs, h, c, attentions)
#define OFF_DEC 0
#define OFF_H   25600000ll
#define OFF_C   25616384ll
#define OFF_ATT 25632768ll

// ---------------- device state ----------------
__device__ float g_h[2][BB * HH];
__device__ float g_c[2][BB * HH];
__device__ float g_x[BB * EE];
__device__ float g_hq[BB * HH];
__device__ float g_gate[BB * FF];
__device__ float g_ctxg[BB * FF];
__device__ float g_encproj[BB * NN * HH];
__device__ float g_gpart[6][BB * G4];
__device__ unsigned long long g_amax[BB];

// ---------------- f32x2 helpers ----------------
__device__ __forceinline__ unsigned long long pk2(float lo, float hi) {
    unsigned long long r;
    asm("mov.b64 %0, {%1,%2};" : "=l"(r) : "f"(lo), "f"(hi));
    return r;
}
__device__ __forceinline__ void upk2(unsigned long long v, float& lo, float& hi) {
    asm("mov.b64 {%0,%1}, %2;" : "=f"(lo), "=f"(hi) : "l"(v));
}
__device__ __forceinline__ void fma2(unsigned long long& d, unsigned long long a,
                                     unsigned long long b) {
    asm("fma.rn.f32x2 %0, %1, %2, %0;" : "+l"(d) : "l"(a), "l"(b));
}

__device__ __forceinline__ float sigf(float x) { return 1.0f / (1.0f + expf(-x)); }

__device__ __forceinline__ unsigned mono32(float f) {
    unsigned u = __float_as_uint(f);
    return (u & 0x80000000u) ? ~u : (u | 0x80000000u);
}

// ---------------- skinny GEMM core: C[32, tile64] += A[32,K] * W[K,N] ----------------
// Block: 256 threads. cg = tid&15 -> 4 cols; rp = tid>>4 -> rows (2rp, 2rp+1).
// acc[c] is an f32x2 pair (row 2rp in lo, row 2rp+1 in hi).
__device__ __forceinline__ void gemm32_tile(
    const float* __restrict__ A, int lda,
    const float* __restrict__ W, int ldw,
    int K, int N, int bcol,
    unsigned long long acc[4], float* s_a)
{
    const int tid = threadIdx.x;
    const int cg = tid & 15;
    const int rp = tid >> 4;
    const int col0 = bcol + cg * 4;
    const bool full = (col0 + 4 <= N);

    for (int k0 = 0; k0 < K; k0 += 64) {
        __syncthreads();
#pragma unroll
        for (int i = 0; i < 8; i++) {
            int idx = tid + i * 256;          // 0..2047
            int kk = idx & 63;
            int row = idx >> 6;               // 0..31
            s_a[kk * 34 + row] = A[(size_t)row * lda + k0 + kk];
        }
        __syncthreads();
        const float* Wp = W + (size_t)k0 * ldw + col0;
#pragma unroll 8
        for (int kk = 0; kk < 64; kk++) {
            float4 w4;
            if (full) {
                w4 = *(const float4*)(Wp + (size_t)kk * ldw);
            } else {
                const float* wr = Wp + (size_t)kk * ldw;
                w4.x = (col0 + 0 < N) ? wr[0] : 0.f;
                w4.y = (col0 + 1 < N) ? wr[1] : 0.f;
                w4.z = (col0 + 2 < N) ? wr[2] : 0.f;
                w4.w = (col0 + 3 < N) ? wr[3] : 0.f;
            }
            unsigned long long a2 =
                *(const unsigned long long*)(s_a + kk * 34 + 2 * rp);
            fma2(acc[0], a2, pk2(w4.x, w4.x));
            fma2(acc[1], a2, pk2(w4.y, w4.y));
            fma2(acc[2], a2, pk2(w4.z, w4.z));
            fma2(acc[3], a2, pk2(w4.w, w4.w));
        }
    }
}

// ---------------- setup kernels ----------------
// enc_proj = features @ W2 + b2   ([B*N, F] @ [F, H])
__global__ void __launch_bounds__(256) k_encproj(const float* __restrict__ feat,
                                                 const float* __restrict__ W2,
                                                 const float* __restrict__ b2)
{
    __shared__ __align__(16) float s_a[64 * 34];
    unsigned long long acc[4] = {0, 0, 0, 0};
    int bcol = blockIdx.x * 64;
    const float* A = feat + (size_t)blockIdx.y * 32 * FF;
    gemm32_tile(A, FF, W2, HH, FF, HH, bcol, acc, s_a);
    float* C = g_encproj + (size_t)blockIdx.y * 32 * HH;
    int cg = threadIdx.x & 15, rp = threadIdx.x >> 4;
    int col = bcol + cg * 4;
#pragma unroll
    for (int c = 0; c < 4; c++) {
        float lo, hi;
        upk2(acc[c], lo, hi);
        float bb = b2[col + c];
        C[(size_t)(2 * rp) * HH + col + c] = lo + bb;
        C[(size_t)(2 * rp + 1) * HH + col + c] = hi + bb;
    }
}

// h0/c0 from mean feature; x0 = emb[SOS]
__global__ void __launch_bounds__(256) k_init(const float* __restrict__ feat,
                                              const float* __restrict__ Wh,
                                              const float* __restrict__ bh,
                                              const float* __restrict__ Wc,
                                              const float* __restrict__ bc,
                                              const float* __restrict__ emb)
{
    __shared__ float s_mean[FF];
    int b = blockIdx.x, tid = threadIdx.x;
    const float* fb = feat + (size_t)b * NN * FF;
    for (int f = tid; f < FF; f += 256) {
        float s = 0.f;
#pragma unroll 4
        for (int n = 0; n < NN; n++) s += fb[(size_t)n * FF + f];
        s_mean[f] = s * (1.0f / NN);
    }
    __syncthreads();
    for (int j = tid; j < HH; j += 256) {
        float ha = bh[j], ca = bc[j];
        for (int f = 0; f < FF; f++) {
            float m = s_mean[f];
            ha = fmaf(m, Wh[(size_t)f * HH + j], ha);
            ca = fmaf(m, Wc[(size_t)f * HH + j], ca);
        }
        g_h[0][b * HH + j] = ha;
        g_c[0][b * HH + j] = ca;
        g_x[b * EE + j] = emb[(size_t)1 * EE + j];   // SOS = 1
    }
}

// ---------------- per-step kernels ----------------
// K_G1: hq = h@W1+b1 ; gate = sigmoid(h@Wg+bg) ; gpart0 = x@WxTop + blstm ; gpart1 = h@Whh
__global__ void __launch_bounds__(256) k_g1(int p,
    const float* __restrict__ W1, const float* __restrict__ b1,
    const float* __restrict__ Wg, const float* __restrict__ bg,
    const float* __restrict__ Wx, const float* __restrict__ Whh,
    const float* __restrict__ blstm)
{
    __shared__ __align__(16) float s_a[64 * 34];
    unsigned long long acc[4] = {0, 0, 0, 0};
    int bx = blockIdx.x;
    int cg = threadIdx.x & 15, rp = threadIdx.x >> 4;
    if (bx < 8) {
        int bcol = bx * 64;
        gemm32_tile(g_h[p], HH, W1, HH, HH, HH, bcol, acc, s_a);
        int col = bcol + cg * 4;
#pragma unroll
        for (int c = 0; c < 4; c++) {
            float lo, hi; upk2(acc[c], lo, hi);
            float bb = b1[col + c];
            g_hq[(2 * rp) * HH + col + c] = lo + bb;
            g_hq[(2 * rp + 1) * HH + col + c] = hi + bb;
        }
    } else if (bx < 28) {
        int bcol = (bx - 8) * 64;
        gemm32_tile(g_h[p], HH, Wg, FF, HH, FF, bcol, acc, s_a);
        int col = bcol + cg * 4;
#pragma unroll
        for (int c = 0; c < 4; c++) {
            float lo, hi; upk2(acc[c], lo, hi);
            float bb = bg[col + c];
            g_gate[(2 * rp) * FF + col + c] = sigf(lo + bb);
            g_gate[(2 * rp + 1) * FF + col + c] = sigf(hi + bb);
        }
    } else {
        int i2 = bx - 28;
        int ct = i2 & 31;
        int ks = i2 >> 5;           // 0: x@WxTop(+blstm), 1: h@Whh
        int bcol = ct * 64;
        if (ks == 0)
            gemm32_tile(g_x, EE, Wx, G4, EE, G4, bcol, acc, s_a);
        else
            gemm32_tile(g_h[p], HH, Whh, G4, HH, G4, bcol, acc, s_a);
        int col = bcol + cg * 4;
        float* C = g_gpart[ks];
#pragma unroll
        for (int c = 0; c < 4; c++) {
            float lo, hi; upk2(acc[c], lo, hi);
            float bb = (ks == 0) ? blstm[col + c] : 0.f;
            C[(2 * rp) * G4 + col + c] = lo + bb;
            C[(2 * rp + 1) * G4 + col + c] = hi + bb;
        }
    }
}

// K_ATT: scores -> softmax -> attentions out ; gated context -> g_ctxg
__global__ void __launch_bounds__(256) k_att(int t, const float* __restrict__ feat,
                                             const float* __restrict__ Va,
                                             float* __restrict__ out)
{
    __shared__ float s_hq[HH], s_va[HH], s_w[NN], s_ms[2];
    int b = blockIdx.x, tid = threadIdx.x;
    for (int j = tid; j < HH; j += 256) { s_hq[j] = g_hq[b * HH + j]; s_va[j] = Va[j]; }
    __syncthreads();
    int w = tid >> 5, lane = tid & 31;
    for (int n = w; n < NN; n += 8) {
        const float* ep = g_encproj + ((size_t)b * NN + n) * HH;
        float s = 0.f;
        for (int j = lane; j < HH; j += 32) {
            float v = s_hq[j] + ep[j];
            s += fmaxf(v, 0.f) * s_va[j];
        }
#pragma unroll
        for (int m = 16; m; m >>= 1) s += __shfl_xor_sync(0xffffffffu, s, m);
        if (lane == 0) s_w[n] = s;
    }
    __syncthreads();
    if (tid == 0) {
        float m = s_w[0];
        for (int n = 1; n < NN; n++) m = fmaxf(m, s_w[n]);
        s_ms[0] = m;
    }
    __syncthreads();
    if (tid < NN) s_w[tid] = __expf(s_w[tid] - s_ms[0]);
    __syncthreads();
    if (tid == 0) {
        float s = 0.f;
        for (int n = 0; n < NN; n++) s += s_w[n];
        s_ms[1] = 1.0f / s;
    }
    __syncthreads();
    if (tid < NN) {
        s_w[tid] *= s_ms[1];
        out[OFF_ATT + ((size_t)b * TT + t) * NN + tid] = s_w[tid];
    }
    __syncthreads();
    const float* fb = feat + (size_t)b * NN * FF;
    for (int f0 = tid; f0 < FF; f0 += 256) {
        float acc = 0.f;
#pragma unroll 4
        for (int n = 0; n < NN; n++) acc += s_w[n] * fb[(size_t)n * FF + f0];
        g_ctxg[b * FF + f0] = acc * g_gate[b * FF + f0];
    }
}

// K_G2: gpart[2+ks] = ctxg(kslice) @ WxBot(kslice)   (4 K-slices of 320)
__global__ void __launch_bounds__(256) k_g2(const float* __restrict__ Wx)
{
    __shared__ __align__(16) float s_a[64 * 34];
    unsigned long long acc[4] = {0, 0, 0, 0};
    int ks = blockIdx.y;
    int bcol = blockIdx.x * 64;
    gemm32_tile(g_ctxg + ks * 320, FF, Wx + (size_t)(EE + ks * 320) * G4, G4,
                320, G4, bcol, acc, s_a);
    int cg = threadIdx.x & 15, rp = threadIdx.x >> 4;
    int col = bcol + cg * 4;
    float* C = g_gpart[2 + ks];
#pragma unroll
    for (int c = 0; c < 4; c++) {
        float lo, hi; upk2(acc[c], lo, hi);
        C[(2 * rp) * G4 + col + c] = lo;
        C[(2 * rp + 1) * G4 + col + c] = hi;
    }
}

// K_LSTM: sum the 6 partials, pointwise LSTM, write h/c (and final outputs). Reset argmax.
__global__ void __launch_bounds__(128) k_lstm(int p, int last, float* __restrict__ out)
{
    int b = blockIdx.x;
    for (int j = threadIdx.x; j < HH; j += 128) {
        float v[4];
#pragma unroll
        for (int g = 0; g < 4; g++) {
            float s = 0.f;
#pragma unroll
            for (int pt = 0; pt < 6; pt++) s += g_gpart[pt][b * G4 + g * HH + j];
            v[g] = s;
        }
        float c_old = g_c[p][b * HH + j];
        float c2 = sigf(v[1]) * c_old + sigf(v[0]) * tanhf(v[2]);
        float h2 = sigf(v[3]) * tanhf(c2);
        g_c[p ^ 1][b * HH + j] = c2;
        g_h[p ^ 1][b * HH + j] = h2;
        if (last) {
            out[OFF_H + b * HH + j] = h2;
            out[OFF_C + b * HH + j] = c2;
        }
    }
    if (threadIdx.x == 0) g_amax[b] = 0ull;
}

// K_OUT: logits = h2 @ Wout + bout; write dec out; atomic argmax per row.
__global__ void __launch_bounds__(256) k_out(int pn, int t,
                                             const float* __restrict__ Wout,
                                             const float* __restrict__ bout,
                                             float* __restrict__ out)
{
    __shared__ __align__(16) float s_a[64 * 34];
    unsigned long long acc[4] = {0, 0, 0, 0};
    int bcol = blockIdx.x * 64;
    gemm32_tile(g_h[pn], HH, Wout, VV, HH, VV, bcol, acc, s_a);
    int tid = threadIdx.x;
    int cg = tid & 15, rp = tid >> 4;
    int col = bcol + cg * 4;
    int r0 = 2 * rp, r1 = r0 + 1;
    unsigned long long best0 = 0ull, best1 = 0ull;
#pragma unroll
    for (int c = 0; c < 4; c++) {
        int cc = col + c;
        if (cc < VV) {
            float lo, hi; upk2(acc[c], lo, hi);
            float bb = bout[cc];
            lo += bb; hi += bb;
            out[((size_t)r0 * TT + t) * VV + cc] = lo;
            out[((size_t)r1 * TT + t) * VV + cc] = hi;
            unsigned long long k0 =
                ((unsigned long long)mono32(lo) << 32) | (0xFFFFFFFFu - (unsigned)cc);
            unsigned long long k1 =
                ((unsigned long long)mono32(hi) << 32) | (0xFFFFFFFFu - (unsigned)cc);
            if (k0 > best0) best0 = k0;
            if (k1 > best1) best1 = k1;
        }
    }
#pragma unroll
    for (int m = 8; m; m >>= 1) {
        unsigned long long o0 = __shfl_xor_sync(0xffffffffu, best0, m, 16);
        unsigned long long o1 = __shfl_xor_sync(0xffffffffu, best1, m, 16);
        if (o0 > best0) best0 = o0;
        if (o1 > best1) best1 = o1;
    }
    if ((tid & 15) == 0) {
        atomicMax(&g_amax[r0], best0);
        atomicMax(&g_amax[r1], best1);
    }
}

// K_EMB: x = emb[argmax]
__global__ void __launch_bounds__(128) k_emb(const float* __restrict__ emb)
{
    int b = blockIdx.x;
    unsigned cc = 0xFFFFFFFFu - (unsigned)(g_amax[b] & 0xFFFFFFFFull);
    for (int e = threadIdx.x; e < EE; e += 128)
        g_x[b * EE + e] = emb[(size_t)cc * EE + e];
}

// ---------------- launch ----------------
extern "C" void kernel_launch(void* const* d_in, const int* in_sizes, int n_in,
                              void* d_out, int out_size)
{
    // metadata order: feature_outputs, caption, [max_caption], emb, W1, b1, W2, b2,
    //                 Va, bVa, Wh, bh, Wc, bc, Wg, bg, Wx, Whh, blstm, Wout, bout
    int off = (n_in >= 21) ? 1 : 0;
    const float* feat  = (const float*)d_in[0];
    const float* emb   = (const float*)d_in[2 + off];
    const float* W1    = (const float*)d_in[3 + off];
    const float* b1    = (const float*)d_in[4 + off];
    const float* W2    = (const float*)d_in[5 + off];
    const float* b2    = (const float*)d_in[6 + off];
    const float* Va    = (const float*)d_in[7 + off];
    const float* Wh    = (const float*)d_in[9 + off];
    const float* bh    = (const float*)d_in[10 + off];
    const float* Wc    = (const float*)d_in[11 + off];
    const float* bc    = (const float*)d_in[12 + off];
    const float* Wg    = (const float*)d_in[13 + off];
    const float* bg    = (const float*)d_in[14 + off];
    const float* Wx    = (const float*)d_in[15 + off];
    const float* Whh   = (const float*)d_in[16 + off];
    const float* blstm = (const float*)d_in[17 + off];
    const float* Wout  = (const float*)d_in[18 + off];
    const float* bout  = (const float*)d_in[19 + off];
    float* out = (float*)d_out;

    k_init<<<BB, 256>>>(feat, Wh, bh, Wc, bc, emb);
    k_encproj<<<dim3(HH / 64, (BB * NN) / 32), 256>>>(feat, W2, b2);

    for (int t = 0; t < TT; t++) {
        int p = t & 1;
        k_g1<<<92, 256>>>(p, W1, b1, Wg, bg, Wx, Whh, blstm);
        k_att<<<BB, 256>>>(t, feat, Va, out);
        k_g2<<<dim3(G4 / 64, 4), 256>>>(Wx);
        k_lstm<<<BB, 128>>>(p, (t == TT - 1) ? 1 : 0, out);
        k_out<<<(VV + 63) / 64, 256>>>(p ^ 1, t, Wout, bout, out);
        k_emb<<<BB, 128>>>(emb);
    }
}

// round 2
// speedup vs baseline: 1.1369x; 1.1369x over previous
#include <cuda_runtime.h>
#include <cuda_bf16.h>
#include <cstdint>

// Problem constants
#define BB 32
#define NN 64
#define FF 1280
#define HH 512
#define EE 512
#define VV 10000
#define TT 80
#define G4 2048          // 4*H

// Output layout (pytree flatten order: decoder_outputs, h, c, attentions)
#define OFF_H   25600000ll
#define OFF_C   25616384ll
#define OFF_ATT 25632768ll

// ---------------- device state ----------------
__device__ float g_h[2][BB * HH];
__device__ float g_c[2][BB * HH];
__device__ float g_hq[BB * HH];
__device__ float g_gate[BB * FF];
__device__ float g_ctxg[BB * FF];
__device__ float g_attw[BB * NN];
__device__ float g_encproj[BB * NN * HH];
__device__ float g_gpart[6][BB * G4];
__device__ unsigned long long g_amax[BB];

// ---------------- f32x2 helpers ----------------
__device__ __forceinline__ unsigned long long pk2(float lo, float hi) {
    unsigned long long r;
    asm("mov.b64 %0, {%1,%2};" : "=l"(r) : "f"(lo), "f"(hi));
    return r;
}
__device__ __forceinline__ void upk2(unsigned long long v, float& lo, float& hi) {
    asm("mov.b64 {%0,%1}, %2;" : "=f"(lo), "=f"(hi) : "l"(v));
}
__device__ __forceinline__ void fma2(unsigned long long& d, unsigned long long a,
                                     unsigned long long b) {
    asm("fma.rn.f32x2 %0, %1, %2, %0;" : "+l"(d) : "l"(a), "l"(b));
}

__device__ __forceinline__ float sigf(float x) { return 1.0f / (1.0f + expf(-x)); }

__device__ __forceinline__ unsigned mono32(float f) {
    unsigned u = __float_as_uint(f);
    return (u & 0x80000000u) ? ~u : (u | 0x80000000u);
}

// ---------------- skinny GEMM core v2 ----------------
// C[32, 64-col tile] = A[32,K] @ W[K,N].  256 threads.
// cg = tid&15 -> 4 cols (as 2 f32x2 pairs straight from the W float4);
// rp = tid>>4 -> rows (2rp, 2rp+1) broadcast from shared A.
// acc[r][p]: row (2rp+r), cols (col0+2p, col0+2p+1).
template <class ARow>
__device__ __forceinline__ void gemm_core(ARow arow,
    const float* __restrict__ W, int ldw,
    int K, int N, int bcol,
    unsigned long long acc[2][2], float* s_a)
{
    const int tid = threadIdx.x;
    const int cg = tid & 15;
    const int rp = tid >> 4;
    const int col0 = bcol + cg * 4;
    const bool full = (col0 + 4 <= N);

    for (int k0 = 0; k0 < K; k0 += 64) {
        __syncthreads();
#pragma unroll
        for (int i = 0; i < 8; i++) {
            int idx = tid + i * 256;          // 0..2047
            int kk = idx & 63;
            int row = idx >> 6;               // 0..31
            s_a[kk * 34 + row] = arow(row)[k0 + kk];
        }
        __syncthreads();
        const float* Wp = W + (size_t)k0 * ldw + col0;
        if (full) {
            for (int kb = 0; kb < 64; kb += 8) {
                float4 wb[8];
#pragma unroll
                for (int u = 0; u < 8; u++)
                    wb[u] = *(const float4*)(Wp + (size_t)(kb + u) * ldw);
#pragma unroll
                for (int u = 0; u < 8; u++) {
                    float2 a2 = *(const float2*)(s_a + (kb + u) * 34 + 2 * rp);
                    unsigned long long a00 = pk2(a2.x, a2.x);
                    unsigned long long a11 = pk2(a2.y, a2.y);
                    unsigned long long w01 = pk2(wb[u].x, wb[u].y);
                    unsigned long long w23 = pk2(wb[u].z, wb[u].w);
                    fma2(acc[0][0], w01, a00);
                    fma2(acc[0][1], w23, a00);
                    fma2(acc[1][0], w01, a11);
                    fma2(acc[1][1], w23, a11);
                }
            }
        } else {
#pragma unroll 4
            for (int kk = 0; kk < 64; kk++) {
                const float* wr = Wp + (size_t)kk * ldw;
                float4 w4;
                w4.x = (col0 + 0 < N) ? wr[0] : 0.f;
                w4.y = (col0 + 1 < N) ? wr[1] : 0.f;
                w4.z = (col0 + 2 < N) ? wr[2] : 0.f;
                w4.w = (col0 + 3 < N) ? wr[3] : 0.f;
                float2 a2 = *(const float2*)(s_a + kk * 34 + 2 * rp);
                unsigned long long a00 = pk2(a2.x, a2.x);
                unsigned long long a11 = pk2(a2.y, a2.y);
                unsigned long long w01 = pk2(w4.x, w4.y);
                unsigned long long w23 = pk2(w4.z, w4.w);
                fma2(acc[0][0], w01, a00);
                fma2(acc[0][1], w23, a00);
                fma2(acc[1][0], w01, a11);
                fma2(acc[1][1], w23, a11);
            }
        }
    }
}

// Epilogue helper: store acc (+bias, optional activation) to C[row*ldc + col].
// act: 0=none, 1=sigmoid
__device__ __forceinline__ void store_tile(unsigned long long acc[2][2],
    float* C, int ldc, int bcol, const float* __restrict__ bias, int act)
{
    int cg = threadIdx.x & 15, rp = threadIdx.x >> 4;
    int col0 = bcol + cg * 4;
#pragma unroll
    for (int p = 0; p < 2; p++) {
        float v0e, v0o, v1e, v1o;
        upk2(acc[0][p], v0e, v0o);
        upk2(acc[1][p], v1e, v1o);
        int ce = col0 + 2 * p, co = ce + 1;
        float be = bias ? bias[ce] : 0.f;
        float bo = bias ? bias[co] : 0.f;
        v0e += be; v0o += bo; v1e += be; v1o += bo;
        if (act == 1) { v0e = sigf(v0e); v0o = sigf(v0o); v1e = sigf(v1e); v1o = sigf(v1o); }
        C[(size_t)(2 * rp) * ldc + ce] = v0e;
        C[(size_t)(2 * rp) * ldc + co] = v0o;
        C[(size_t)(2 * rp + 1) * ldc + ce] = v1e;
        C[(size_t)(2 * rp + 1) * ldc + co] = v1o;
    }
}

// ---------------- setup kernels ----------------
__global__ void __launch_bounds__(256) k_encproj(const float* __restrict__ feat,
                                                 const float* __restrict__ W2,
                                                 const float* __restrict__ b2)
{
    __shared__ __align__(16) float s_a[64 * 34];
    unsigned long long acc[2][2] = {{0, 0}, {0, 0}};
    int bcol = blockIdx.x * 64;
    const float* A = feat + (size_t)blockIdx.y * 32 * FF;
    gemm_core([&](int row) { return A + (size_t)row * FF; }, W2, HH, FF, HH, bcol, acc, s_a);
    store_tile(acc, g_encproj + (size_t)blockIdx.y * 32 * HH, HH, bcol, b2, 0);
}

__global__ void __launch_bounds__(256) k_init(const float* __restrict__ feat,
                                              const float* __restrict__ Wh,
                                              const float* __restrict__ bh,
                                              const float* __restrict__ Wc,
                                              const float* __restrict__ bc)
{
    __shared__ float s_mean[FF];
    int b = blockIdx.x, tid = threadIdx.x;
    const float* fb = feat + (size_t)b * NN * FF;
    for (int f = tid; f < FF; f += 256) {
        float s = 0.f;
#pragma unroll 8
        for (int n = 0; n < NN; n++) s += fb[(size_t)n * FF + f];
        s_mean[f] = s * (1.0f / NN);
    }
    __syncthreads();
    for (int j = tid; j < HH; j += 256) {
        float ha = bh[j], ca = bc[j];
#pragma unroll 4
        for (int f = 0; f < FF; f++) {
            float m = s_mean[f];
            ha = fmaf(m, Wh[(size_t)f * HH + j], ha);
            ca = fmaf(m, Wc[(size_t)f * HH + j], ca);
        }
        g_h[0][b * HH + j] = ha;
        g_c[0][b * HH + j] = ca;
    }
    if (tid == 0) g_amax[b] = (unsigned long long)(0xFFFFFFFFu - 1u);  // token = SOS = 1
}

// ---------------- per-step kernels ----------------
// K_G1: hq = h@W1+b1 ; gate = sigmoid(h@Wg+bg) ; gpart0 = emb[tok]@WxTop + blstm ; gpart1 = h@Whh
__global__ void __launch_bounds__(256) k_g1(int p, const float* __restrict__ emb,
    const float* __restrict__ W1, const float* __restrict__ b1,
    const float* __restrict__ Wg, const float* __restrict__ bg,
    const float* __restrict__ Wx, const float* __restrict__ Whh,
    const float* __restrict__ blstm)
{
    __shared__ __align__(16) float s_a[64 * 34];
    __shared__ unsigned s_tok[32];
    unsigned long long acc[2][2] = {{0, 0}, {0, 0}};
    int bx = blockIdx.x;
    if (bx < 8) {
        int bcol = bx * 64;
        gemm_core([&](int row) { return &g_h[p][row * HH]; }, W1, HH, HH, HH, bcol, acc, s_a);
        store_tile(acc, g_hq, HH, bcol, b1, 0);
    } else if (bx < 28) {
        int bcol = (bx - 8) * 64;
        gemm_core([&](int row) { return &g_h[p][row * HH]; }, Wg, FF, HH, FF, bcol, acc, s_a);
        store_tile(acc, g_gate, FF, bcol, bg, 1);
    } else if (bx < 60) {
        // x @ WxTop + blstm, x = emb[token]
        if (threadIdx.x < 32)
            s_tok[threadIdx.x] =
                0xFFFFFFFFu - (unsigned)(g_amax[threadIdx.x] & 0xFFFFFFFFull);
        int bcol = (bx - 28) * 64;
        gemm_core([&](int row) { return emb + (size_t)s_tok[row] * EE; },
                  Wx, G4, EE, G4, bcol, acc, s_a);
        store_tile(acc, g_gpart[0], G4, bcol, blstm, 0);
    } else {
        int bcol = (bx - 60) * 64;
        gemm_core([&](int row) { return &g_h[p][row * HH]; }, Whh, G4, HH, G4, bcol, acc, s_a);
        store_tile(acc, g_gpart[1], G4, bcol, nullptr, 0);
    }
}

// K_SCORE: Bahdanau scores -> softmax -> attn out + g_attw
__global__ void __launch_bounds__(256) k_score(int t, const float* __restrict__ Va,
                                               float* __restrict__ out)
{
    __shared__ float s_hq[HH], s_va[HH], s_w[NN], s_ms[2];
    int b = blockIdx.x, tid = threadIdx.x;
    for (int j = tid; j < HH; j += 256) { s_hq[j] = g_hq[b * HH + j]; s_va[j] = Va[j]; }
    __syncthreads();
    int w = tid >> 5, lane = tid & 31;
    for (int n = w; n < NN; n += 8) {
        const float* ep = g_encproj + ((size_t)b * NN + n) * HH;
        float s = 0.f;
#pragma unroll 4
        for (int j = lane; j < HH; j += 32) {
            float v = s_hq[j] + ep[j];
            s += fmaxf(v, 0.f) * s_va[j];
        }
#pragma unroll
        for (int m = 16; m; m >>= 1) s += __shfl_xor_sync(0xffffffffu, s, m);
        if (lane == 0) s_w[n] = s;
    }
    __syncthreads();
    if (tid == 0) {
        float m = s_w[0];
        for (int n = 1; n < NN; n++) m = fmaxf(m, s_w[n]);
        s_ms[0] = m;
    }
    __syncthreads();
    if (tid < NN) s_w[tid] = __expf(s_w[tid] - s_ms[0]);
    __syncthreads();
    if (tid == 0) {
        float s = 0.f;
        for (int n = 0; n < NN; n++) s += s_w[n];
        s_ms[1] = 1.0f / s;
    }
    __syncthreads();
    if (tid < NN) {
        float wv = s_w[tid] * s_ms[1];
        g_attw[b * NN + tid] = wv;
        out[OFF_ATT + ((size_t)b * TT + t) * NN + tid] = wv;
    }
}

// K_CTX: gated context.  grid (FF/128, B), 128 threads, one F col per thread.
__global__ void __launch_bounds__(128) k_ctx(const float* __restrict__ feat)
{
    __shared__ float s_w[NN];
    int b = blockIdx.y, tid = threadIdx.x;
    int f = blockIdx.x * 128 + tid;
    if (tid < NN) s_w[tid] = g_attw[b * NN + tid];
    __syncthreads();
    const float* fb = feat + (size_t)b * NN * FF + f;
    float acc = 0.f;
#pragma unroll 8
    for (int n = 0; n < NN; n++) acc += s_w[n] * fb[(size_t)n * FF];
    g_ctxg[b * FF + f] = acc * g_gate[b * FF + f];
}

// K_G2: gpart[2+ks] = ctxg(kslice) @ WxBot(kslice)   (4 K-slices of 320)
__global__ void __launch_bounds__(256) k_g2(const float* __restrict__ Wx)
{
    __shared__ __align__(16) float s_a[64 * 34];
    unsigned long long acc[2][2] = {{0, 0}, {0, 0}};
    int ks = blockIdx.y;
    int bcol = blockIdx.x * 64;
    const float* Wp = Wx + (size_t)(EE + ks * 320) * G4;
    gemm_core([&](int row) { return g_ctxg + row * FF + ks * 320; },
              Wp, G4, 320, G4, bcol, acc, s_a);
    store_tile(acc, g_gpart[2 + ks], G4, bcol, nullptr, 0);
}

// K_LSTM: sum 6 partials, pointwise LSTM, write h/c (+final out). Reset argmax.
__global__ void __launch_bounds__(128) k_lstm(int p, int last, float* __restrict__ out)
{
    int b = blockIdx.x;
    for (int j = threadIdx.x; j < HH; j += 128) {
        float v[4];
#pragma unroll
        for (int g = 0; g < 4; g++) {
            float s = 0.f;
#pragma unroll
            for (int pt = 0; pt < 6; pt++) s += g_gpart[pt][b * G4 + g * HH + j];
            v[g] = s;
        }
        float c_old = g_c[p][b * HH + j];
        float c2 = sigf(v[1]) * c_old + sigf(v[0]) * tanhf(v[2]);
        float h2 = sigf(v[3]) * tanhf(c2);
        g_c[p ^ 1][b * HH + j] = c2;
        g_h[p ^ 1][b * HH + j] = h2;
        if (last) {
            out[OFF_H + b * HH + j] = h2;
            out[OFF_C + b * HH + j] = c2;
        }
    }
    if (threadIdx.x == 0) g_amax[b] = 0ull;
}

// K_OUT: logits = h2 @ Wout + bout; write dec out; atomic packed argmax per row.
__global__ void __launch_bounds__(256) k_out(int pn, int t,
                                             const float* __restrict__ Wout,
                                             const float* __restrict__ bout,
                                             float* __restrict__ out)
{
    __shared__ __align__(16) float s_a[64 * 34];
    unsigned long long acc[2][2] = {{0, 0}, {0, 0}};
    int bcol = blockIdx.x * 64;
    gemm_core([&](int row) { return &g_h[pn][row * HH]; }, Wout, VV, HH, VV, bcol, acc, s_a);
    int tid = threadIdx.x;
    int cg = tid & 15, rp = tid >> 4;
    int col0 = bcol + cg * 4;
    int r0 = 2 * rp, r1 = r0 + 1;
    unsigned long long best0 = 0ull, best1 = 0ull;
#pragma unroll
    for (int ppp = 0; ppp < 2; ppp++) {
        float v0e, v0o, v1e, v1o;
        upk2(acc[0][ppp], v0e, v0o);
        upk2(acc[1][ppp], v1e, v1o);
        int ce = col0 + 2 * ppp, co = ce + 1;
        float vv[2][2] = {{v0e, v0o}, {v1e, v1o}};
        int cc[2] = {ce, co};
#pragma unroll
        for (int q = 0; q < 2; q++) {
            if (cc[q] < VV) {
                float lo = vv[0][q] + bout[cc[q]];
                float hi = vv[1][q] + bout[cc[q]];
                out[((size_t)r0 * TT + t) * VV + cc[q]] = lo;
                out[((size_t)r1 * TT + t) * VV + cc[q]] = hi;
                unsigned long long k0 =
                    ((unsigned long long)mono32(lo) << 32) | (0xFFFFFFFFu - (unsigned)cc[q]);
                unsigned long long k1 =
                    ((unsigned long long)mono32(hi) << 32) | (0xFFFFFFFFu - (unsigned)cc[q]);
                if (k0 > best0) best0 = k0;
                if (k1 > best1) best1 = k1;
            }
        }
    }
#pragma unroll
    for (int m = 8; m; m >>= 1) {
        unsigned long long o0 = __shfl_xor_sync(0xffffffffu, best0, m, 16);
        unsigned long long o1 = __shfl_xor_sync(0xffffffffu, best1, m, 16);
        if (o0 > best0) best0 = o0;
        if (o1 > best1) best1 = o1;
    }
    if ((tid & 15) == 0) {
        atomicMax(&g_amax[r0], best0);
        atomicMax(&g_amax[r1], best1);
    }
}

// ---------------- launch ----------------
extern "C" void kernel_launch(void* const* d_in, const int* in_sizes, int n_in,
                              void* d_out, int out_size)
{
    int off = (n_in >= 21) ? 1 : 0;
    const float* feat  = (const float*)d_in[0];
    const float* emb   = (const float*)d_in[2 + off];
    const float* W1    = (const float*)d_in[3 + off];
    const float* b1    = (const float*)d_in[4 + off];
    const float* W2    = (const float*)d_in[5 + off];
    const float* b2    = (const float*)d_in[6 + off];
    const float* Va    = (const float*)d_in[7 + off];
    const float* Wh    = (const float*)d_in[9 + off];
    const float* bh    = (const float*)d_in[10 + off];
    const float* Wc    = (const float*)d_in[11 + off];
    const float* bc    = (const float*)d_in[12 + off];
    const float* Wg    = (const float*)d_in[13 + off];
    const float* bg    = (const float*)d_in[14 + off];
    const float* Wx    = (const float*)d_in[15 + off];
    const float* Whh   = (const float*)d_in[16 + off];
    const float* blstm = (const float*)d_in[17 + off];
    const float* Wout  = (const float*)d_in[18 + off];
    const float* bout  = (const float*)d_in[19 + off];
    float* out = (float*)d_out;

    k_init<<<BB, 256>>>(feat, Wh, bh, Wc, bc);
    k_encproj<<<dim3(HH / 64, (BB * NN) / 32), 256>>>(feat, W2, b2);

    for (int t = 0; t < TT; t++) {
        int p = t & 1;
        k_g1<<<92, 256>>>(p, emb, W1, b1, Wg, bg, Wx, Whh, blstm);
        k_score<<<BB, 256>>>(t, Va, out);
        k_ctx<<<dim3(FF / 128, BB), 128>>>(feat);
        k_g2<<<dim3(G4 / 64, 4), 256>>>(Wx);
        k_lstm<<<BB, 128>>>(p, (t == TT - 1) ? 1 : 0, out);
        k_out<<<(VV + 63) / 64, 256>>>(p ^ 1, t, Wout, bout, out);
    }
}

// round 3
// speedup vs baseline: 1.9535x; 1.7182x over previous
#include <cuda_runtime.h>
#include <cuda_bf16.h>
#include <cstdint>

#define BB 32
#define NN 64
#define FF 1280
#define HH 512
#define EE 512
#define VV 10000
#define TT 80
#define G4 2048

#define OFF_H   25600000ll
#define OFF_C   25616384ll
#define OFF_ATT 25632768ll

// ---------------- device state ----------------
__device__ float g_h[2][BB * HH];
__device__ float g_c[2][BB * HH];
__device__ float g_hq[BB * HH];
__device__ float g_gate[BB * FF];
__device__ float g_ctx[BB * FF];
__device__ float g_attw[BB * NN];
__device__ float g_encproj[BB * NN * HH];
__device__ float g_gpart[6][BB * G4];
__device__ unsigned long long g_amax[BB];

// ---------------- helpers ----------------
__device__ __forceinline__ unsigned long long pk2(float lo, float hi) {
    unsigned long long r;
    asm("mov.b64 %0, {%1,%2};" : "=l"(r) : "f"(lo), "f"(hi));
    return r;
}
__device__ __forceinline__ void upk2(unsigned long long v, float& lo, float& hi) {
    asm("mov.b64 {%0,%1}, %2;" : "=f"(lo), "=f"(hi) : "l"(v));
}
__device__ __forceinline__ void fma2(unsigned long long& d, unsigned long long a,
                                     unsigned long long b) {
    asm("fma.rn.f32x2 %0, %1, %2, %0;" : "+l"(d) : "l"(a), "l"(b));
}
__device__ __forceinline__ float sigf(float x) { return 1.0f / (1.0f + expf(-x)); }
__device__ __forceinline__ unsigned mono32(float f) {
    unsigned u = __float_as_uint(f);
    return (u & 0x80000000u) ? ~u : (u | 0x80000000u);
}

// ---------------- GEMM core v3 ----------------
// C[32, 64-col tile] = A[32,K] @ W[K,N].  512 threads, 16 warps.
// warp (tid>>5) -> row pair (2w, 2w+1); lane (tid&31) -> col pair.
// acc[r] = f32x2 over (col0, col0+1) for row 2w+r.
template <class AElem>
__device__ __forceinline__ void gemm_core(AElem aelem,
    const float* __restrict__ W, int ldw,
    int K, int N, int bcol,
    unsigned long long acc[2], float* s_a)
{
    const int tid = threadIdx.x;
    const int cg = tid & 31;
    const int rp = tid >> 5;
    const int col0 = bcol + cg * 2;
    const bool full = (col0 + 2 <= N);

    for (int k0 = 0; k0 < K; k0 += 64) {
        __syncthreads();
#pragma unroll
        for (int i = 0; i < 4; i++) {
            int idx = tid + i * 512;          // 0..2047
            int kk = idx & 63;
            int row = idx >> 6;               // 0..31
            s_a[kk * 34 + row] = aelem(row, k0 + kk);
        }
        __syncthreads();
        const float* Wp = W + (size_t)k0 * ldw + col0;
        if (full) {
#pragma unroll 1
            for (int kb = 0; kb < 64; kb += 8) {
                float2 wb[8];
#pragma unroll
                for (int u = 0; u < 8; u++)
                    wb[u] = *(const float2*)(Wp + (size_t)(kb + u) * ldw);
#pragma unroll
                for (int u = 0; u < 8; u++) {
                    float2 a2 = *(const float2*)(s_a + (kb + u) * 34 + 2 * rp);
                    unsigned long long w01 = pk2(wb[u].x, wb[u].y);
                    fma2(acc[0], w01, pk2(a2.x, a2.x));
                    fma2(acc[1], w01, pk2(a2.y, a2.y));
                }
            }
        } else {
#pragma unroll 4
            for (int kk = 0; kk < 64; kk++) {
                const float* wr = Wp + (size_t)kk * ldw;
                float wx = (col0 + 0 < N) ? wr[0] : 0.f;
                float wy = (col0 + 1 < N) ? wr[1] : 0.f;
                float2 a2 = *(const float2*)(s_a + kk * 34 + 2 * rp);
                unsigned long long w01 = pk2(wx, wy);
                fma2(acc[0], w01, pk2(a2.x, a2.x));
                fma2(acc[1], w01, pk2(a2.y, a2.y));
            }
        }
    }
}

// Epilogue: +bias, optional sigmoid, store (with N guard).
__device__ __forceinline__ void store_tile(unsigned long long acc[2],
    float* C, int ldc, int bcol, int N, const float* __restrict__ bias, int act)
{
    int cg = threadIdx.x & 31, rp = threadIdx.x >> 5;
    int col0 = bcol + cg * 2;
    float v0, v1, u0, u1;
    upk2(acc[0], v0, v1);   // row 2rp
    upk2(acc[1], u0, u1);   // row 2rp+1
#pragma unroll
    for (int q = 0; q < 2; q++) {
        int cc = col0 + q;
        if (cc >= N) continue;
        float a = (q == 0) ? v0 : v1;
        float b = (q == 0) ? u0 : u1;
        float bb = bias ? bias[cc] : 0.f;
        a += bb; b += bb;
        if (act == 1) { a = sigf(a); b = sigf(b); }
        C[(size_t)(2 * rp) * ldc + cc] = a;
        C[(size_t)(2 * rp + 1) * ldc + cc] = b;
    }
}

// ---------------- setup ----------------
__global__ void __launch_bounds__(512) k_encproj(const float* __restrict__ feat,
                                                 const float* __restrict__ W2,
                                                 const float* __restrict__ b2)
{
    __shared__ __align__(16) float s_a[64 * 34];
    unsigned long long acc[2] = {0, 0};
    int bcol = blockIdx.x * 64;
    const float* A = feat + (size_t)blockIdx.y * 32 * FF;
    gemm_core([&](int row, int k) { return A[(size_t)row * FF + k]; },
              W2, HH, FF, HH, bcol, acc, s_a);
    store_tile(acc, g_encproj + (size_t)blockIdx.y * 32 * HH, HH, bcol, HH, b2, 0);
}

__global__ void __launch_bounds__(256) k_init(const float* __restrict__ feat,
                                              const float* __restrict__ Wh,
                                              const float* __restrict__ bh,
                                              const float* __restrict__ Wc,
                                              const float* __restrict__ bc)
{
    __shared__ float s_mean[FF];
    int b = blockIdx.x, tid = threadIdx.x;
    const float* fb = feat + (size_t)b * NN * FF;
    for (int f = tid; f < FF; f += 256) {
        float s = 0.f;
#pragma unroll 8
        for (int n = 0; n < NN; n++) s += fb[(size_t)n * FF + f];
        s_mean[f] = s * (1.0f / NN);
    }
    __syncthreads();
    for (int j = tid; j < HH; j += 256) {
        float ha = bh[j], ca = bc[j];
#pragma unroll 4
        for (int f = 0; f < FF; f++) {
            float m = s_mean[f];
            ha = fmaf(m, Wh[(size_t)f * HH + j], ha);
            ca = fmaf(m, Wc[(size_t)f * HH + j], ca);
        }
        g_h[0][b * HH + j] = ha;
        g_c[0][b * HH + j] = ca;
    }
    if (tid == 0) g_amax[b] = (unsigned long long)(0xFFFFFFFFu - 1u);  // SOS=1
}

// ---------------- per-step ----------------
// K_G1: hq = h@W1+b1 ; gate = sig(h@Wg+bg) ; gpart0 = emb[tok]@WxTop+blstm ; gpart1 = h@Whh
__global__ void __launch_bounds__(512) k_g1(int p, const float* __restrict__ emb,
    const float* __restrict__ W1, const float* __restrict__ b1,
    const float* __restrict__ Wg, const float* __restrict__ bg,
    const float* __restrict__ Wx, const float* __restrict__ Whh,
    const float* __restrict__ blstm)
{
    __shared__ __align__(16) float s_a[64 * 34];
    __shared__ unsigned s_tok[32];
    unsigned long long acc[2] = {0, 0};
    int bx = blockIdx.x;
    if (bx < 8) {
        int bcol = bx * 64;
        gemm_core([&](int r, int k) { return g_h[p][r * HH + k]; },
                  W1, HH, HH, HH, bcol, acc, s_a);
        store_tile(acc, g_hq, HH, bcol, HH, b1, 0);
    } else if (bx < 28) {
        int bcol = (bx - 8) * 64;
        gemm_core([&](int r, int k) { return g_h[p][r * HH + k]; },
                  Wg, FF, HH, FF, bcol, acc, s_a);
        store_tile(acc, g_gate, FF, bcol, FF, bg, 1);
    } else if (bx < 60) {
        if (threadIdx.x < 32)
            s_tok[threadIdx.x] =
                0xFFFFFFFFu - (unsigned)(g_amax[threadIdx.x] & 0xFFFFFFFFull);
        int bcol = (bx - 28) * 64;
        gemm_core([&](int r, int k) { return emb[(size_t)s_tok[r] * EE + k]; },
                  Wx, G4, EE, G4, bcol, acc, s_a);
        store_tile(acc, g_gpart[0], G4, bcol, G4, blstm, 0);
    } else {
        int bcol = (bx - 60) * 64;
        gemm_core([&](int r, int k) { return g_h[p][r * HH + k]; },
                  Whh, G4, HH, G4, bcol, acc, s_a);
        store_tile(acc, g_gpart[1], G4, bcol, G4, nullptr, 0);
    }
}

// K_ATT: scores (vectorized) -> softmax -> attn out ; raw context -> g_ctx
__global__ void __launch_bounds__(512) k_att(int t, const float* __restrict__ Va,
                                             const float* __restrict__ feat,
                                             float* __restrict__ out)
{
    __shared__ __align__(16) float s_hq[HH];
    __shared__ __align__(16) float s_va[HH];
    __shared__ float s_w[NN], s_red[4];
    int b = blockIdx.x, tid = threadIdx.x;
    int w = tid >> 5, lane = tid & 31;
    for (int j = tid; j < HH; j += 512) { s_hq[j] = g_hq[b * HH + j]; s_va[j] = Va[j]; }
    __syncthreads();
    // scores: 16 warps x 4 rows each, float4 loads
#pragma unroll
    for (int q = 0; q < 4; q++) {
        int n = w + 16 * q;
        const float4* ep = (const float4*)(g_encproj + ((size_t)b * NN + n) * HH);
        float s = 0.f;
#pragma unroll
        for (int i = 0; i < 4; i++) {
            int e4 = lane + 32 * i;            // float4 index within row
            float4 v = ep[e4];
            float4 hq4 = *(const float4*)(s_hq + e4 * 4);
            float4 va4 = *(const float4*)(s_va + e4 * 4);
            s += fmaxf(v.x + hq4.x, 0.f) * va4.x;
            s += fmaxf(v.y + hq4.y, 0.f) * va4.y;
            s += fmaxf(v.z + hq4.z, 0.f) * va4.z;
            s += fmaxf(v.w + hq4.w, 0.f) * va4.w;
        }
#pragma unroll
        for (int m = 16; m; m >>= 1) s += __shfl_xor_sync(0xffffffffu, s, m);
        if (lane == 0) s_w[n] = s;
    }
    __syncthreads();
    // softmax over 64 (two warps)
    if (tid < 64) {
        float v = s_w[tid];
        float m = v;
#pragma unroll
        for (int s = 16; s; s >>= 1) m = fmaxf(m, __shfl_xor_sync(0xffffffffu, m, s));
        if (lane == 0) s_red[tid >> 5] = m;
        __syncwarp();
    }
    __syncthreads();
    float gmax = fmaxf(s_red[0], s_red[1]);
    if (tid < 64) {
        float e = __expf(s_w[tid] - gmax);
        s_w[tid] = e;
        float sum = e;
#pragma unroll
        for (int s = 16; s; s >>= 1) sum += __shfl_xor_sync(0xffffffffu, sum, s);
        if (lane == 0) s_red[2 + (tid >> 5)] = sum;
    }
    __syncthreads();
    float inv = 1.0f / (s_red[2] + s_red[3]);
    if (tid < 64) {
        float wv = s_w[tid] * inv;
        s_w[tid] = wv;
        g_attw[b * NN + tid] = wv;
        out[OFF_ATT + ((size_t)b * TT + t) * NN + tid] = wv;
    }
    __syncthreads();
    // raw context (gate applied later in k_g2)
    const float* fb = feat + (size_t)b * NN * FF;
    for (int f = tid; f < FF; f += 512) {
        float a = 0.f;
#pragma unroll 8
        for (int n = 0; n < NN; n++) a += s_w[n] * fb[(size_t)n * FF + f];
        g_ctx[b * FF + f] = a;
    }
}

// K_G2: gpart[2+ks] = (ctx*gate)(kslice) @ WxBot(kslice)   (4 K-slices of 320)
__global__ void __launch_bounds__(512) k_g2(const float* __restrict__ Wx)
{
    __shared__ __align__(16) float s_a[64 * 34];
    unsigned long long acc[2] = {0, 0};
    int ks = blockIdx.y;
    int bcol = blockIdx.x * 64;
    const float* Wp = Wx + (size_t)(EE + ks * 320) * G4;
    int koff = ks * 320;
    gemm_core([&](int r, int k) {
                  int idx = r * FF + koff + k;
                  return g_ctx[idx] * g_gate[idx];
              },
              Wp, G4, 320, G4, bcol, acc, s_a);
    store_tile(acc, g_gpart[2 + ks], G4, bcol, G4, nullptr, 0);
}

// K_LSTM: sum 6 partials (fixed order), pointwise LSTM, write h/c. Reset argmax.
__global__ void __launch_bounds__(256) k_lstm(int p, int last, float* __restrict__ out)
{
    int b = blockIdx.x;
    for (int j = threadIdx.x; j < HH; j += 256) {
        float v[4];
#pragma unroll
        for (int g = 0; g < 4; g++) {
            float s = 0.f;
#pragma unroll
            for (int pt = 0; pt < 6; pt++) s += g_gpart[pt][b * G4 + g * HH + j];
            v[g] = s;
        }
        float c_old = g_c[p][b * HH + j];
        float c2 = sigf(v[1]) * c_old + sigf(v[0]) * tanhf(v[2]);
        float h2 = sigf(v[3]) * tanhf(c2);
        g_c[p ^ 1][b * HH + j] = c2;
        g_h[p ^ 1][b * HH + j] = h2;
        if (last) {
            out[OFF_H + b * HH + j] = h2;
            out[OFF_C + b * HH + j] = c2;
        }
    }
    if (threadIdx.x == 0) g_amax[b] = 0ull;
}

// K_OUT: logits = h2@Wout + bout; write dec out; packed-argmax per row.
__global__ void __launch_bounds__(512) k_out(int pn, int t,
                                             const float* __restrict__ Wout,
                                             const float* __restrict__ bout,
                                             float* __restrict__ out)
{
    __shared__ __align__(16) float s_a[64 * 34];
    unsigned long long acc[2] = {0, 0};
    int bcol = blockIdx.x * 64;
    gemm_core([&](int r, int k) { return g_h[pn][r * HH + k]; },
              Wout, VV, HH, VV, bcol, acc, s_a);
    int tid = threadIdx.x;
    int cg = tid & 31, rp = tid >> 5;       // each warp = one row pair
    int col0 = bcol + cg * 2;
    int r0 = 2 * rp, r1 = r0 + 1;
    float v0, v1, u0, u1;
    upk2(acc[0], v0, v1);
    upk2(acc[1], u0, u1);
    unsigned long long best0 = 0ull, best1 = 0ull;
#pragma unroll
    for (int q = 0; q < 2; q++) {
        int cc = col0 + q;
        if (cc < VV) {
            float lo = ((q == 0) ? v0 : v1) + bout[cc];
            float hi = ((q == 0) ? u0 : u1) + bout[cc];
            out[((size_t)r0 * TT + t) * VV + cc] = lo;
            out[((size_t)r1 * TT + t) * VV + cc] = hi;
            unsigned long long k0 =
                ((unsigned long long)mono32(lo) << 32) | (0xFFFFFFFFu - (unsigned)cc);
            unsigned long long k1 =
                ((unsigned long long)mono32(hi) << 32) | (0xFFFFFFFFu - (unsigned)cc);
            if (k0 > best0) best0 = k0;
            if (k1 > best1) best1 = k1;
        }
    }
#pragma unroll
    for (int m = 16; m; m >>= 1) {
        unsigned long long o0 = __shfl_xor_sync(0xffffffffu, best0, m);
        unsigned long long o1 = __shfl_xor_sync(0xffffffffu, best1, m);
        if (o0 > best0) best0 = o0;
        if (o1 > best1) best1 = o1;
    }
    if (cg == 0) {
        atomicMax(&g_amax[r0], best0);
        atomicMax(&g_amax[r1], best1);
    }
}

// ---------------- launch ----------------
extern "C" void kernel_launch(void* const* d_in, const int* in_sizes, int n_in,
                              void* d_out, int out_size)
{
    int off = (n_in >= 21) ? 1 : 0;
    const float* feat  = (const float*)d_in[0];
    const float* emb   = (const float*)d_in[2 + off];
    const float* W1    = (const float*)d_in[3 + off];
    const float* b1    = (const float*)d_in[4 + off];
    const float* W2    = (const float*)d_in[5 + off];
    const float* b2    = (const float*)d_in[6 + off];
    const float* Va    = (const float*)d_in[7 + off];
    const float* Wh    = (const float*)d_in[9 + off];
    const float* bh    = (const float*)d_in[10 + off];
    const float* Wc    = (const float*)d_in[11 + off];
    const float* bc    = (const float*)d_in[12 + off];
    const float* Wg    = (const float*)d_in[13 + off];
    const float* bg    = (const float*)d_in[14 + off];
    const float* Wx    = (const float*)d_in[15 + off];
    const float* Whh   = (const float*)d_in[16 + off];
    const float* blstm = (const float*)d_in[17 + off];
    const float* Wout  = (const float*)d_in[18 + off];
    const float* bout  = (const float*)d_in[19 + off];
    float* out = (float*)d_out;

    k_init<<<BB, 256>>>(feat, Wh, bh, Wc, bc);
    k_encproj<<<dim3(HH / 64, (BB * NN) / 32), 512>>>(feat, W2, b2);

    for (int t = 0; t < TT; t++) {
        int p = t & 1;
        k_g1<<<92, 512>>>(p, emb, W1, b1, Wg, bg, Wx, Whh, blstm);
        k_att<<<BB, 512>>>(t, Va, feat, out);
        k_g2<<<dim3(G4 / 64, 4), 512>>>(Wx);
        k_lstm<<<BB, 256>>>(p, (t == TT - 1) ? 1 : 0, out);
        k_out<<<(VV + 63) / 64, 512>>>(p ^ 1, t, Wout, bout, out);
    }
}